// round 13
// baseline (speedup 1.0000x reference)
#include <cuda_runtime.h>

// LearnedPosMapT: out[b,w,m,v,s] = sum_n table[m-n+7, s] * x[b,w,n,v,s] + bias[m]
// Shapes: x (8, 3136, 8, 384) f32, table (15, 8) f32, bias (1, 8, 1) f32.
// W = 8 (window), GAMMA = s = 8, v = 48, DIM = v*s = 384.
//
// Memory-bound (616 MB total). One thread per (window, d/4) float4 column:
// 8 coalesced float4 loads, 64 FMA4, 8 coalesced float4 stores.
// R11 change: weights+bias moved to smem (frees ~68 regs) so occupancy rises
// from 2 to 3 CTAs/SM -> more LDG.128 in flight -> higher DRAM utilization.

#define WINSZ 8
#define DIMSZ 384
#define VEC   (DIMSZ / 4)   // 96 float4 per row
#define ROWF4 VEC           // float4 stride between window rows

__global__ __launch_bounds__(256, 3)
void lpm_kernel(const float* __restrict__ x,
                const float* __restrict__ table,   // (15, 8)
                const float* __restrict__ bias,    // (8)
                float* __restrict__ out,
                int n_win)                          // B * NWIN
{
    // Block-shared weight table: wts[s0/4][k] = table[k][s0 .. s0+3].
    // Only 2 distinct s0 variants (0 and 4) across the whole problem.
    __shared__ float4 wts[2][15];
    __shared__ float  bs[WINSZ];

    const int tid = threadIdx.x;
    if (tid < 30) {
        const int sel = tid / 15;
        const int k   = tid - sel * 15;
        wts[sel][k] = *reinterpret_cast<const float4*>(table + k * 8 + sel * 4);
    }
    if (tid < WINSZ) bs[tid] = bias[tid];
    __syncthreads();

    const int t = blockIdx.x * blockDim.x + tid;
    const int total = n_win * VEC;
    if (t >= total) return;

    const int win = t / VEC;
    const int c   = t - win * VEC;        // float4 column index within a row
    const int sel = c & 1;                // (c*4)&7 ? 1 : 0  -> s0/4

    const float4* __restrict__ xin =
        reinterpret_cast<const float4*>(x) + (size_t)win * (WINSZ * ROWF4) + c;
    float4* __restrict__ o =
        reinterpret_cast<float4*>(out) + (size_t)win * (WINSZ * ROWF4) + c;

    // Front-batched x loads: MLP = 8, each warp-coalesced to a 128B line.
    float4 xv[WINSZ];
#pragma unroll
    for (int n = 0; n < WINSZ; n++)
        xv[n] = xin[n * ROWF4];

#pragma unroll
    for (int m = 0; m < WINSZ; m++) {
        const float bm = bs[m];
        float4 acc = make_float4(bm, bm, bm, bm);
#pragma unroll
        for (int n = 0; n < WINSZ; n++) {
            const float4 w = wts[sel][m - n + 7];  // LDS.128, 2-addr broadcast
            acc.x = fmaf(w.x, xv[n].x, acc.x);
            acc.y = fmaf(w.y, xv[n].y, acc.y);
            acc.z = fmaf(w.z, xv[n].z, acc.z);
            acc.w = fmaf(w.w, xv[n].w, acc.w);
        }
        o[m * ROWF4] = acc;
    }
}

extern "C" void kernel_launch(void* const* d_in, const int* in_sizes, int n_in,
                              void* d_out, int out_size) {
    const float* x     = (const float*)d_in[0];   // (B, NWIN, WIN, DIM)
    const float* table = (const float*)d_in[1];   // (15, 8)
    const float* bias  = (const float*)d_in[2];   // (1, 8, 1)
    float* out = (float*)d_out;

    const int n_win = in_sizes[0] / (WINSZ * DIMSZ);   // B * NWIN = 25088
    const int total_threads = n_win * VEC;             // 2,408,448
    const int block = 256;
    const int grid  = (total_threads + block - 1) / block;

    lpm_kernel<<<grid, block>>>(x, table, bias, out, n_win);
}

// round 14
// speedup vs baseline: 1.1041x; 1.1041x over previous
#include <cuda_runtime.h>

// LearnedPosMapT: out[b,w,m,v,s] = sum_n table[m-n+7, s] * x[b,w,n,v,s] + bias[m]
// Shapes: x (8, 3136, 8, 384) f32, table (15, 8) f32, bias (1, 8, 1) f32.
// W = 8 (window), GAMMA = s = 8, v = 48, DIM = v*s = 384.
//
// Memory-bound (616 MB). One thread per (window, d/4) float4 column:
// 8 coalesced float4 loads, 64 FMA4, 8 coalesced float4 stores.
//
// R14: sliding-window weight ring. Output row m needs table rows m..m+7 only,
// so keep 8 weight float4s in a register ring and prefetch ONE new row from
// smem per m-step (issued a full inner loop before first use). Cuts weight
// register residency 60 -> 36, enabling 3 CTAs/SM for more loads in flight.

#define WINSZ 8
#define DIMSZ 384
#define VEC   (DIMSZ / 4)   // 96 float4 per row
#define ROWF4 VEC           // float4 stride between window rows

__global__ __launch_bounds__(256, 3)
void lpm_kernel(const float* __restrict__ x,
                const float* __restrict__ table,   // (15, 8)
                const float* __restrict__ bias,    // (8)
                float* __restrict__ out,
                int n_win)                          // B * NWIN
{
    // Block-shared weight table: wts[s0/4][k] = table[k][s0 .. s0+3].
    __shared__ float4 wts[2][16];
    __shared__ float  bs[WINSZ];

    const int tid = threadIdx.x;
    if (tid < 30) {
        const int sel = tid / 15;
        const int k   = tid - sel * 15;
        wts[sel][k] = *reinterpret_cast<const float4*>(table + k * 8 + sel * 4);
    }
    if (tid < WINSZ) bs[tid] = bias[tid];
    __syncthreads();

    const int t = blockIdx.x * blockDim.x + tid;
    const int total = n_win * VEC;
    if (t >= total) return;

    const int win = t / VEC;
    const int c   = t - win * VEC;        // float4 column index within a row
    const int sel = c & 1;                // s0/4: which half of gamma

    const float4* __restrict__ xin =
        reinterpret_cast<const float4*>(x) + (size_t)win * (WINSZ * ROWF4) + c;
    float4* __restrict__ o =
        reinterpret_cast<float4*>(out) + (size_t)win * (WINSZ * ROWF4) + c;

    // Front-batched x loads: MLP = 8, each warp-coalesced to a 128B line.
    float4 xv[WINSZ];
#pragma unroll
    for (int n = 0; n < WINSZ; n++)
        xv[n] = xin[n * ROWF4];

    // Weight ring: slot (r & 7) holds table row r. Init rows 0..7 (used by m=0).
    float4 wt[8];
#pragma unroll
    for (int j = 0; j < 8; j++)
        wt[j] = wts[sel][j];

#pragma unroll
    for (int m = 0; m < WINSZ; m++) {
        // Prefetch row m+8 (needed first at iteration m+1) into a temp now,
        // so the LDS latency is covered by this iteration's 32 FMAs.
        float4 nxt;
        if (m < WINSZ - 1) nxt = wts[sel][m + 8];

        const float bm = bs[m];
        float4 acc = make_float4(bm, bm, bm, bm);
#pragma unroll
        for (int n = 0; n < WINSZ; n++) {
            const float4 w = wt[(m - n + 7) & 7];   // row m-n+7, compile-time slot
            acc.x = fmaf(w.x, xv[n].x, acc.x);
            acc.y = fmaf(w.y, xv[n].y, acc.y);
            acc.z = fmaf(w.z, xv[n].z, acc.z);
            acc.w = fmaf(w.w, xv[n].w, acc.w);
        }
        o[m * ROWF4] = acc;

        // Row m is dead after this iteration; slide the window.
        if (m < WINSZ - 1) wt[m & 7] = nxt;
    }
}

extern "C" void kernel_launch(void* const* d_in, const int* in_sizes, int n_in,
                              void* d_out, int out_size) {
    const float* x     = (const float*)d_in[0];   // (B, NWIN, WIN, DIM)
    const float* table = (const float*)d_in[1];   // (15, 8)
    const float* bias  = (const float*)d_in[2];   // (1, 8, 1)
    float* out = (float*)d_out;

    const int n_win = in_sizes[0] / (WINSZ * DIMSZ);   // B * NWIN = 25088
    const int total_threads = n_win * VEC;             // 2,408,448
    const int block = 256;
    const int grid  = (total_threads + block - 1) / block;

    lpm_kernel<<<grid, block>>>(x, table, bias, out, n_win);
}

// round 15
// speedup vs baseline: 1.1044x; 1.0003x over previous
#include <cuda_runtime.h>

// LearnedPosMapT: out[b,w,m,v,s] = sum_n table[m-n+7, s] * x[b,w,n,v,s] + bias[m]
// Shapes: x (8, 3136, 8, 384) f32, table (15, 8) f32, bias (1, 8, 1) f32.
// W = 8 (window), GAMMA = s = 8, v = 48, DIM = v*s = 384.
//
// Memory-bound (616 MB). One thread per (window, d/4) float4 column:
// 8 coalesced float4 loads, 64 FMA4, 8 coalesced float4 stores.
//
// R14: sliding-window weight ring. Output row m needs table rows m..m+7 only,
// so keep 8 weight float4s in a register ring and prefetch ONE new row from
// smem per m-step (issued a full inner loop before first use). Cuts weight
// register residency 60 -> 36, enabling 3 CTAs/SM for more loads in flight.

#define WINSZ 8
#define DIMSZ 384
#define VEC   (DIMSZ / 4)   // 96 float4 per row
#define ROWF4 VEC           // float4 stride between window rows

__global__ __launch_bounds__(256, 3)
void lpm_kernel(const float* __restrict__ x,
                const float* __restrict__ table,   // (15, 8)
                const float* __restrict__ bias,    // (8)
                float* __restrict__ out,
                int n_win)                          // B * NWIN
{
    // Block-shared weight table: wts[s0/4][k] = table[k][s0 .. s0+3].
    __shared__ float4 wts[2][16];
    __shared__ float  bs[WINSZ];

    const int tid = threadIdx.x;
    if (tid < 30) {
        const int sel = tid / 15;
        const int k   = tid - sel * 15;
        wts[sel][k] = *reinterpret_cast<const float4*>(table + k * 8 + sel * 4);
    }
    if (tid < WINSZ) bs[tid] = bias[tid];
    __syncthreads();

    const int t = blockIdx.x * blockDim.x + tid;
    const int total = n_win * VEC;
    if (t >= total) return;

    const int win = t / VEC;
    const int c   = t - win * VEC;        // float4 column index within a row
    const int sel = c & 1;                // s0/4: which half of gamma

    const float4* __restrict__ xin =
        reinterpret_cast<const float4*>(x) + (size_t)win * (WINSZ * ROWF4) + c;
    float4* __restrict__ o =
        reinterpret_cast<float4*>(out) + (size_t)win * (WINSZ * ROWF4) + c;

    // Front-batched x loads: MLP = 8, each warp-coalesced to a 128B line.
    float4 xv[WINSZ];
#pragma unroll
    for (int n = 0; n < WINSZ; n++)
        xv[n] = xin[n * ROWF4];

    // Weight ring: slot (r & 7) holds table row r. Init rows 0..7 (used by m=0).
    float4 wt[8];
#pragma unroll
    for (int j = 0; j < 8; j++)
        wt[j] = wts[sel][j];

#pragma unroll
    for (int m = 0; m < WINSZ; m++) {
        // Prefetch row m+8 (needed first at iteration m+1) into a temp now,
        // so the LDS latency is covered by this iteration's 32 FMAs.
        float4 nxt;
        if (m < WINSZ - 1) nxt = wts[sel][m + 8];

        const float bm = bs[m];
        float4 acc = make_float4(bm, bm, bm, bm);
#pragma unroll
        for (int n = 0; n < WINSZ; n++) {
            const float4 w = wt[(m - n + 7) & 7];   // row m-n+7, compile-time slot
            acc.x = fmaf(w.x, xv[n].x, acc.x);
            acc.y = fmaf(w.y, xv[n].y, acc.y);
            acc.z = fmaf(w.z, xv[n].z, acc.z);
            acc.w = fmaf(w.w, xv[n].w, acc.w);
        }
        o[m * ROWF4] = acc;

        // Row m is dead after this iteration; slide the window.
        if (m < WINSZ - 1) wt[m & 7] = nxt;
    }
}

extern "C" void kernel_launch(void* const* d_in, const int* in_sizes, int n_in,
                              void* d_out, int out_size) {
    const float* x     = (const float*)d_in[0];   // (B, NWIN, WIN, DIM)
    const float* table = (const float*)d_in[1];   // (15, 8)
    const float* bias  = (const float*)d_in[2];   // (1, 8, 1)
    float* out = (float*)d_out;

    const int n_win = in_sizes[0] / (WINSZ * DIMSZ);   // B * NWIN = 25088
    const int total_threads = n_win * VEC;             // 2,408,448
    const int block = 256;
    const int grid  = (total_threads + block - 1) / block;

    lpm_kernel<<<grid, block>>>(x, table, bias, out, n_win);
}

// round 16
// speedup vs baseline: 1.1738x; 1.0628x over previous
#include <cuda_runtime.h>

// LearnedPosMapT: out[b,w,m,v,s] = sum_n table[m-n+7, s] * x[b,w,n,v,s] + bias[m]
// Shapes: x (8, 3136, 8, 384) f32, table (15, 8) f32, bias (1, 8, 1) f32.
// W = 8 (window), GAMMA = s = 8, v = 48, DIM = v*s = 384.
//
// Memory-bound (616 MB compulsory). R15: TWO windows per thread (block=128,
// 3 CTAs/SM) — weights stay in registers (smem variants regressed: LDS shares
// the L1tex pipe with the global stream), amortized over 2x traffic, and
// MLP/thread doubles to 16 front-batched LDG.128 -> ~192 lines in flight/SM.
// Streaming cache hints (__ldcs/__stcs): zero-reuse stream.

#define WINSZ 8
#define DIMSZ 384
#define VEC   (DIMSZ / 4)   // 96 float4 per row
#define ROWF4 VEC           // float4 stride between window rows
#define WINF4 (WINSZ * ROWF4)

__global__ __launch_bounds__(128, 3)
void lpm_kernel(const float* __restrict__ x,
                const float* __restrict__ table,   // (15, 8)
                const float* __restrict__ bias,    // (8)
                float* __restrict__ out,
                int n_pair)                         // (B * NWIN) / 2
{
    const int t = blockIdx.x * blockDim.x + threadIdx.x;
    const int total = n_pair * VEC;
    if (t >= total) return;

    const int pair = t / VEC;
    const int c    = t - pair * VEC;      // float4 column index within a row
    const int s0   = (c * 4) & 7;         // starting gamma index (0 or 4)

    const float4* __restrict__ xin0 =
        reinterpret_cast<const float4*>(x) + (size_t)pair * (2 * WINF4) + c;
    const float4* __restrict__ xin1 = xin0 + WINF4;
    float4* __restrict__ o0 =
        reinterpret_cast<float4*>(out) + (size_t)pair * (2 * WINF4) + c;
    float4* __restrict__ o1 = o0 + WINF4;

    // 15 weight rows in registers: table[k][s0..s0+3], 16B aligned.
    // L1/L2-resident broadcast after the first warp touches them.
    float4 wt[15];
#pragma unroll
    for (int k = 0; k < 15; k++)
        wt[k] = *reinterpret_cast<const float4*>(table + k * 8 + s0);

    float bm[WINSZ];
#pragma unroll
    for (int m = 0; m < WINSZ; m++)
        bm[m] = bias[m];

    // Front-batched x loads for BOTH windows: MLP = 16, each warp-coalesced.
    float4 xv0[WINSZ], xv1[WINSZ];
#pragma unroll
    for (int n = 0; n < WINSZ; n++)
        xv0[n] = __ldcs(xin0 + n * ROWF4);
#pragma unroll
    for (int n = 0; n < WINSZ; n++)
        xv1[n] = __ldcs(xin1 + n * ROWF4);

#pragma unroll
    for (int m = 0; m < WINSZ; m++) {
        float4 a0 = make_float4(bm[m], bm[m], bm[m], bm[m]);
        float4 a1 = a0;
#pragma unroll
        for (int n = 0; n < WINSZ; n++) {
            const float4 w = wt[m - n + 7];
            a0.x = fmaf(w.x, xv0[n].x, a0.x);
            a0.y = fmaf(w.y, xv0[n].y, a0.y);
            a0.z = fmaf(w.z, xv0[n].z, a0.z);
            a0.w = fmaf(w.w, xv0[n].w, a0.w);
            a1.x = fmaf(w.x, xv1[n].x, a1.x);
            a1.y = fmaf(w.y, xv1[n].y, a1.y);
            a1.z = fmaf(w.z, xv1[n].z, a1.z);
            a1.w = fmaf(w.w, xv1[n].w, a1.w);
        }
        __stcs(o0 + m * ROWF4, a0);
        __stcs(o1 + m * ROWF4, a1);
    }
}

extern "C" void kernel_launch(void* const* d_in, const int* in_sizes, int n_in,
                              void* d_out, int out_size) {
    const float* x     = (const float*)d_in[0];   // (B, NWIN, WIN, DIM)
    const float* table = (const float*)d_in[1];   // (15, 8)
    const float* bias  = (const float*)d_in[2];   // (1, 8, 1)
    float* out = (float*)d_out;

    const int n_win  = in_sizes[0] / (WINSZ * DIMSZ);  // B * NWIN = 25088 (even)
    const int n_pair = n_win / 2;                      // 12544
    const int total_threads = n_pair * VEC;            // 1,204,224
    const int block = 128;
    const int grid  = (total_threads + block - 1) / block;  // 9408

    lpm_kernel<<<grid, block>>>(x, table, bias, out, n_pair);
}

// round 17
// speedup vs baseline: 1.1928x; 1.0162x over previous
#include <cuda_runtime.h>

// LearnedPosMapT: out[b,w,m,v,s] = sum_n table[m-n+7, s] * x[b,w,n,v,s] + bias[m]
// Shapes: x (8, 3136, 8, 384) f32, table (15, 8) f32, bias (1, 8, 1) f32.
// W = 8 (window), GAMMA = s = 8, v = 48, DIM = v*s = 384.
//
// Memory-bound (616 MB compulsory). R15: TWO windows per thread (block=128,
// 3 CTAs/SM) — weights stay in registers (smem variants regressed: LDS shares
// the L1tex pipe with the global stream), amortized over 2x traffic, and
// MLP/thread doubles to 16 front-batched LDG.128 -> ~192 lines in flight/SM.
// Streaming cache hints (__ldcs/__stcs): zero-reuse stream.

#define WINSZ 8
#define DIMSZ 384
#define VEC   (DIMSZ / 4)   // 96 float4 per row
#define ROWF4 VEC           // float4 stride between window rows
#define WINF4 (WINSZ * ROWF4)

__global__ __launch_bounds__(128, 3)
void lpm_kernel(const float* __restrict__ x,
                const float* __restrict__ table,   // (15, 8)
                const float* __restrict__ bias,    // (8)
                float* __restrict__ out,
                int n_pair)                         // (B * NWIN) / 2
{
    const int t = blockIdx.x * blockDim.x + threadIdx.x;
    const int total = n_pair * VEC;
    if (t >= total) return;

    const int pair = t / VEC;
    const int c    = t - pair * VEC;      // float4 column index within a row
    const int s0   = (c * 4) & 7;         // starting gamma index (0 or 4)

    const float4* __restrict__ xin0 =
        reinterpret_cast<const float4*>(x) + (size_t)pair * (2 * WINF4) + c;
    const float4* __restrict__ xin1 = xin0 + WINF4;
    float4* __restrict__ o0 =
        reinterpret_cast<float4*>(out) + (size_t)pair * (2 * WINF4) + c;
    float4* __restrict__ o1 = o0 + WINF4;

    // 15 weight rows in registers: table[k][s0..s0+3], 16B aligned.
    // L1/L2-resident broadcast after the first warp touches them.
    float4 wt[15];
#pragma unroll
    for (int k = 0; k < 15; k++)
        wt[k] = *reinterpret_cast<const float4*>(table + k * 8 + s0);

    float bm[WINSZ];
#pragma unroll
    for (int m = 0; m < WINSZ; m++)
        bm[m] = bias[m];

    // Front-batched x loads for BOTH windows: MLP = 16, each warp-coalesced.
    float4 xv0[WINSZ], xv1[WINSZ];
#pragma unroll
    for (int n = 0; n < WINSZ; n++)
        xv0[n] = __ldcs(xin0 + n * ROWF4);
#pragma unroll
    for (int n = 0; n < WINSZ; n++)
        xv1[n] = __ldcs(xin1 + n * ROWF4);

#pragma unroll
    for (int m = 0; m < WINSZ; m++) {
        float4 a0 = make_float4(bm[m], bm[m], bm[m], bm[m]);
        float4 a1 = a0;
#pragma unroll
        for (int n = 0; n < WINSZ; n++) {
            const float4 w = wt[m - n + 7];
            a0.x = fmaf(w.x, xv0[n].x, a0.x);
            a0.y = fmaf(w.y, xv0[n].y, a0.y);
            a0.z = fmaf(w.z, xv0[n].z, a0.z);
            a0.w = fmaf(w.w, xv0[n].w, a0.w);
            a1.x = fmaf(w.x, xv1[n].x, a1.x);
            a1.y = fmaf(w.y, xv1[n].y, a1.y);
            a1.z = fmaf(w.z, xv1[n].z, a1.z);
            a1.w = fmaf(w.w, xv1[n].w, a1.w);
        }
        __stcs(o0 + m * ROWF4, a0);
        __stcs(o1 + m * ROWF4, a1);
    }
}

extern "C" void kernel_launch(void* const* d_in, const int* in_sizes, int n_in,
                              void* d_out, int out_size) {
    const float* x     = (const float*)d_in[0];   // (B, NWIN, WIN, DIM)
    const float* table = (const float*)d_in[1];   // (15, 8)
    const float* bias  = (const float*)d_in[2];   // (1, 8, 1)
    float* out = (float*)d_out;

    const int n_win  = in_sizes[0] / (WINSZ * DIMSZ);  // B * NWIN = 25088 (even)
    const int n_pair = n_win / 2;                      // 12544
    const int total_threads = n_pair * VEC;            // 1,204,224
    const int block = 128;
    const int grid  = (total_threads + block - 1) / block;  // 9408

    lpm_kernel<<<grid, block>>>(x, table, bias, out, n_pair);
}